// round 13
// baseline (speedup 1.0000x reference)
#include <cuda_runtime.h>
#include <cuda_bf16.h>

#define BB    64
#define NN    25200
#define TOPK  1024
#define CAP   2048
#define NBINS 1024
#define CONF  0.25f
#define IOUT  0.45f
#define CHUNK 788          // ceil(25200/32)
#define PB    8            // pairs blocks per image
#define SCAP  256          // scan row-cache capacity
#define SSTR  36           // cache row stride (words): 16B-aligned

// ---------------- scratch (device globals: allocation-free) ----------------
__device__ float        g_scores[BB * NN];
__device__ unsigned int g_hist[BB * NBINS];
__device__ int          g_topidx[BB * TOPK];
__device__ float        g_topscore[BB * TOPK];
__device__ float4       g_sbox[BB * TOPK];
__device__ uint2        g_saux[BB * TOPK];
__device__ int          g_cellstart[BB * 257];
__device__ unsigned int g_mask[BB * TOPK * 32];
__device__ unsigned int g_wnz[BB * TOPK];
__device__ int          g_done[BB];

// ---------------- K1: WIDE score + histogram (HBM-floor read) ----------------
__global__ __launch_bounds__(256) void k_score(const float* __restrict__ x) {
    int b = blockIdx.y;
#pragma unroll
    for (int a = 0; a < 4; ++a) {
        int n = blockIdx.x * 1024 + a * 256 + threadIdx.x;
        if (n < NN) {
            const float4* row = (const float4*)(x + (long)(b * NN + n) * 16);
            float s = row[1].x * row[3].w;
            g_scores[b * NN + n] = s;
            if (s > CONF) {
                int bin = min((int)((s - CONF) * (1024.0f / 0.75f)), NBINS - 1);
                atomicAdd(&g_hist[b * NBINS + bin], 1u);
            }
        }
    }
}

// ---------------- K2: threshold + compact + sort(2048) + bin ----------------
__global__ __launch_bounds__(1024) void k_topk(const float* __restrict__ x) {
    __shared__ unsigned int shist[NBINS];
    __shared__ unsigned long long sk[CAP];
    __shared__ int sT, wcnt[32], woff[32];
    __shared__ int counts[256], scanbuf[256], cstart[257];

    int b = blockIdx.x, t = threadIdx.x;
    int w = t >> 5, lane = t & 31;

    shist[t] = g_hist[b * NBINS + t];
    g_hist[b * NBINS + t] = 0u;          // replay-safe reset
    if (t == 0) sT = 0;
    __syncthreads();
    for (int off = 1; off < NBINS; off <<= 1) {
        unsigned int v = (t + off < NBINS) ? shist[t + off] : 0u;
        __syncthreads();
        shist[t] += v;
        __syncthreads();
    }
    if (shist[t] >= TOPK) atomicMax(&sT, t);
    sk[t] = 0ULL; sk[t + 1024] = 0ULL;
    __syncthreads();

    int T = sT;
    int base = w * CHUNK;
    int lim = min(base + CHUNK, NN);
    {
        int cnt = 0;
        for (int it = 0; it < 25; ++it) {
            int n = base + it * 32 + lane;
            bool sel = false;
            if (n < lim) {
                float s = g_scores[b * NN + n];
                if (s > CONF) {
                    int bin = min((int)((s - CONF) * (1024.0f / 0.75f)), NBINS - 1);
                    sel = (bin >= T);
                }
            }
            cnt += __popc(__ballot_sync(0xffffffffu, sel));
        }
        if (lane == 0) wcnt[w] = cnt;
    }
    __syncthreads();
    if (t < 32) {
        int v = wcnt[t], p = v;
#pragma unroll
        for (int off = 1; off < 32; off <<= 1) {
            int y = __shfl_up_sync(0xffffffffu, p, off);
            if (t >= off) p += y;
        }
        woff[t] = p - v;
    }
    __syncthreads();
    {
        int off = woff[w];
        int run = 0;
        for (int it = 0; it < 25; ++it) {
            int n = base + it * 32 + lane;
            bool sel = false;
            float s = 0.0f;
            if (n < lim) {
                s = g_scores[b * NN + n];
                if (s > CONF) {
                    int bin = min((int)((s - CONF) * (1024.0f / 0.75f)), NBINS - 1);
                    sel = (bin >= T);
                }
            }
            unsigned int m = __ballot_sync(0xffffffffu, sel);
            if (sel) {
                int pos = off + run + __popc(m & ((1u << lane) - 1u));
                if (pos < CAP) {
                    sk[pos] = ((unsigned long long)__float_as_uint(s) << 32) |
                              (unsigned long long)(0xFFFFFFFFu - (unsigned)n);
                }
            }
            run += __popc(m);
        }
    }
    __syncthreads();

    for (int k = 2; k <= CAP; k <<= 1) {
        for (int j = k >> 1; j > 0; j >>= 1) {
            for (int e = t; e < CAP; e += 1024) {
                int ixj = e ^ j;
                if (ixj > e) {
                    unsigned long long a = sk[e], c = sk[ixj];
                    bool desc = ((e & k) == 0);
                    if (desc ? (a < c) : (a > c)) { sk[e] = c; sk[ixj] = a; }
                }
            }
            __syncthreads();
        }
    }

    unsigned long long key = sk[t];
    float sc = __uint_as_float((unsigned)(key >> 32));
    int idx = (key == 0ULL) ? 0 : (int)(0xFFFFFFFFu - (unsigned)(key & 0xFFFFFFFFu));
    if (idx < 0 || idx >= NN) idx = 0;
    g_topscore[b * TOPK + t] = (key == 0ULL) ? 0.0f : sc;
    g_topidx[b * TOPK + t] = idx;
    const float4* row = (const float4*)(x + (long)(b * NN + idx) * 16);
    float4 c0 = row[0];
    float hw = c0.z * 0.5f, hh = c0.w * 0.5f;
    float4 box = make_float4(c0.x - hw, c0.y - hh, c0.x + hw, c0.y + hh);
    float sv = 0.45f * (fmaxf(box.z - box.x, 0.0f) * fmaxf(box.w - box.y, 0.0f));
    int cellx = min(15, max(0, (int)(c0.x * 0.025f)));
    int celly = min(15, max(0, (int)(c0.y * 0.025f)));
    int cell = celly * 16 + cellx;

    if (t < 256) counts[t] = 0;
    __syncthreads();
    atomicAdd(&counts[cell], 1);
    __syncthreads();
    if (t < 256) scanbuf[t] = counts[t];
    __syncthreads();
    for (int off = 1; off < 256; off <<= 1) {
        int add = 0;
        if (t < 256 && t >= off) add = scanbuf[t - off];
        __syncthreads();
        if (t < 256) scanbuf[t] += add;
        __syncthreads();
    }
    if (t == 0) cstart[0] = 0;
    if (t < 256) { cstart[t + 1] = scanbuf[t]; counts[t] = (t == 0) ? 0 : scanbuf[t - 1]; }
    __syncthreads();
    {
        int pos = atomicAdd(&counts[cell], 1);
        g_sbox[b * TOPK + pos] = box;
        g_saux[b * TOPK + pos] = make_uint2(__float_as_uint(sv), (unsigned)t);
    }
    if (t < 257) g_cellstart[b * 257 + t] = cstart[t];
}

// ---------------- K3: pairs; the LAST block of each image also scans --------
struct PairsSmem {
    float4       sbox[TOPK];        // 16384
    uint2        sax[TOPK];         // 8192
    int          cs[257];           // 1028
    unsigned int rows[128 * 33];    // 16896
};
struct ScanSmem {
    unsigned int scomp[SCAP * SSTR];            // 36864
    int          sslot[TOPK];                   // 4096
    unsigned int validw[32], harw[32], keepw[32];
    int          woffw[32];
};

__global__ __launch_bounds__(512) void k_pairs(const float* __restrict__ x,
                                               float* __restrict__ out) {
    __shared__ union { PairsSmem p; ScanSmem s; } u;
    __shared__ int lastFlag;
    int bid = blockIdx.x, t = threadIdx.x;
    int w = t >> 5, lane = t & 31;
    int b = bid >> 3;

    // ================= PAIRS phase =================
    {
        int le = t >> 2;                  // local entry 0..127
        int q  = t & 3;                   // quarter
        int s  = (bid & 7) * 128 + le;    // spatial entry

        for (int e = t; e < TOPK; e += 512) {
            u.p.sbox[e] = g_sbox[b * TOPK + e];
            u.p.sax[e]  = g_saux[b * TOPK + e];
        }
        for (int e = t; e < 257; e += 512) u.p.cs[e] = g_cellstart[b * 257 + e];
        __syncthreads();

        unsigned int* rowp = &u.p.rows[le * 33];
        for (int ww = q; ww < 32; ww += 4) rowp[ww] = 0u;
        __syncwarp();

        float4 bs = u.p.sbox[s];
        uint2 axs = u.p.sax[s];
        float uu = __uint_as_float(axs.x);
        int rs = (int)axs.y;

        int cl = max(0, (int)((bs.x - 64.5f) * 0.025f));
        int cr = min(15, (int)((bs.z + 64.5f) * 0.025f));
        int ct = max(0, (int)((bs.y - 64.5f) * 0.025f));
        int cb = min(15, (int)((bs.w + 64.5f) * 0.025f));

        for (int cy = ct; cy <= cb; ++cy) {
            int e0 = u.p.cs[cy * 16 + cl];
            int e1 = u.p.cs[cy * 16 + cr + 1];
#pragma unroll 2
            for (int e = e0 + q; e < e1; e += 4) {
                float4 be = u.p.sbox[e];
                uint2 axe = u.p.sax[e];
                float ix1 = fmaxf(bs.x, be.x), iy1 = fmaxf(bs.y, be.y);
                float ix2 = fminf(bs.z, be.z), iy2 = fminf(bs.w, be.w);
                float inter = fmaxf(ix2 - ix1, 0.0f) * fmaxf(iy2 - iy1, 0.0f);
                float sden = uu + __uint_as_float(axe.x);
                float diff = fmaf(1.45f, inter, -sden);
                bool bit;
                if (fabsf(diff) <= 2e-5f * sden) {   // rare: exact IEEE path
                    float ai = fmaxf(bs.z - bs.x, 0.0f) * fmaxf(bs.w - bs.y, 0.0f);
                    float aj = fmaxf(be.z - be.x, 0.0f) * fmaxf(be.w - be.y, 0.0f);
                    float den = (ai + aj - inter) + 1e-9f;
                    bit = (__fdiv_rn(inter, den) > IOUT);
                } else {
                    bit = (diff > 0.0f);
                }
                int re = (int)axe.y;
                if (bit && re > rs) atomicOr(&rowp[re >> 5], 1u << (re & 31));
            }
        }
        __syncwarp();

        if (q == 0) {
            unsigned int wm = 0u;
#pragma unroll
            for (int ww = 0; ww < 32; ++ww) wm |= (rowp[ww] != 0u) ? (1u << ww) : 0u;
            g_wnz[b * TOPK + rs] = wm;
            if (wm) {
                unsigned int* orow = &g_mask[((long)(b * TOPK + rs)) * 32];
#pragma unroll
                for (int ww = 0; ww < 32; ++ww) orow[ww] = rowp[ww];
            }
        }
    }

    // ================= last-block ticket (release/acquire) =================
    __threadfence();          // release: our g_mask/g_wnz visible before ticket
    __syncthreads();
    if (t == 0) {
        int old = atomicAdd(&g_done[b], 1);
        lastFlag = (old == PB - 1) ? 1 : 0;
        if (old == PB - 1) g_done[b] = 0;   // replay-safe reset
        __threadfence();      // acquire for subsequent reads
    }
    __syncthreads();
    if (!lastFlag) return;

    // ================= SCAN phase (last block only; smem reused) ==========
    {
        bool va = g_topscore[b * TOPK + t] > 0.0f;
        unsigned int bv = __ballot_sync(0xffffffffu, va);
        if (lane == 0) u.s.validw[w] = bv;
        bool vb2 = g_topscore[b * TOPK + t + 512] > 0.0f;
        bv = __ballot_sync(0xffffffffu, vb2);
        if (lane == 0) u.s.validw[16 + w] = bv;

        bool ha = g_wnz[b * TOPK + t] != 0u;
        unsigned int bh = __ballot_sync(0xffffffffu, ha);
        if (lane == 0) u.s.harw[w] = bh;
        bool hb2 = g_wnz[b * TOPK + t + 512] != 0u;
        bh = __ballot_sync(0xffffffffu, hb2);
        if (lane == 0) u.s.harw[16 + w] = bh;
    }
    __syncthreads();
    if (t < 32) {
        int v = __popc(u.s.harw[t]), p = v;
#pragma unroll
        for (int off = 1; off < 32; off <<= 1) {
            int y = __shfl_up_sync(0xffffffffu, p, off);
            if (t >= off) p += y;
        }
        u.s.woffw[t] = p - v;   // exclusive prefix of nonzero-row counts
    }
    __syncthreads();

    // compact nonzero rows (ascending rank) into smem cache, cap SCAP
    for (int r = t; r < TOPK; r += 512) {
        unsigned int hw2 = u.s.harw[r >> 5];
        if ((hw2 >> (r & 31)) & 1u) {
            int slot = u.s.woffw[r >> 5] + __popc(hw2 & ((1u << (r & 31)) - 1u));
            u.s.sslot[r] = (slot < SCAP) ? slot : -1;
            if (slot < SCAP) {
                const uint4* src = (const uint4*)&g_mask[((long)(b * TOPK + r)) * 32];
                uint4* dst = (uint4*)&u.s.scomp[slot * SSTR];
#pragma unroll
                for (int i = 0; i < 8; ++i) dst[i] = src[i];
            }
        }
    }
    __syncthreads();

    // serial greedy scan (warp 0)
    if (t < 32) {
        unsigned int removed = 0u;
        unsigned int vwl = u.s.validw[lane];
        for (int wi = 0; wi < 32; ++wi) {
            unsigned int alive = __shfl_sync(0xffffffffu, vwl & ~removed, wi);
            unsigned int evt = alive & u.s.harw[wi];
            while (evt) {
                int j = __ffs(evt) - 1;                    // warp-uniform
                evt &= evt - 1u;
                int r = (wi << 5) + j;
                int sj = u.s.sslot[r];                     // uniform LDS
                unsigned int rw, au;
                if (sj >= 0) {
                    rw = u.s.scomp[sj * SSTR + lane];      // per-lane LDS
                    au = u.s.scomp[sj * SSTR + wi];        // uniform LDS broadcast
                } else {                                   // rare overflow: L2
                    const unsigned int* gr = &g_mask[((long)(b * TOPK + r)) * 32];
                    rw = gr[lane];
                    au = gr[wi];
                }
                removed |= rw;
                alive &= ~au;
                evt &= alive;
            }
            if (lane == 0) u.s.keepw[wi] = alive;
        }
    }
    __syncthreads();

    // output: 512 threads x 2 ranks
    for (int r = t; r < TOPK; r += 512) {
        unsigned int kept = (u.s.keepw[r >> 5] >> (r & 31)) & 1u;
        float4* orow = (float4*)(out + (long)(b * TOPK + r) * 16);
        if (kept) {
            int oidx = g_topidx[b * TOPK + r];
            float osc = g_topscore[b * TOPK + r];
            const float4* row = (const float4*)(x + (long)(b * NN + oidx) * 16);
            float4 d0 = row[0], d1 = row[1], d2 = row[2], d3 = row[3];
            float hw2 = d0.z * 0.5f, hh2 = d0.w * 0.5f;
            orow[0] = make_float4(d0.x - hw2, d0.y - hh2, d0.x + hw2, d0.y + hh2);
            orow[1] = make_float4(osc, d1.y, d1.z, d1.w);
            orow[2] = d2;
            orow[3] = make_float4(d3.x, d3.y, d3.z, 0.0f);
        } else {
            float4 z = make_float4(0.0f, 0.0f, 0.0f, 0.0f);
            orow[0] = z; orow[1] = z; orow[2] = z; orow[3] = z;
        }
    }
}

// ---------------- launch ----------------
extern "C" void kernel_launch(void* const* d_in, const int* in_sizes, int n_in,
                              void* d_out, int out_size) {
    const float* x = (const float*)d_in[0];
    float* out = (float*)d_out;
    (void)in_sizes; (void)n_in; (void)out_size;

    {
        dim3 g((NN + 1023) / 1024, BB);
        k_score<<<g, 256>>>(x);
    }
    k_topk<<<BB, 1024>>>(x);
    k_pairs<<<PB * BB, 512>>>(x, out);
}

// round 14
// speedup vs baseline: 1.2274x; 1.2274x over previous
#include <cuda_runtime.h>
#include <cuda_bf16.h>

#define BB    64
#define NN    25200
#define TOPK  1024
#define CAP   2048
#define NBINS 1024
#define CONF  0.25f
#define IOUT  0.45f
#define CHUNK 788          // ceil(25200/32)
#define RSTR  36           // srow stride (words): conflict-free + 16B aligned

// ---------------- scratch (device globals: allocation-free) ----------------
__device__ float        g_scores[BB * NN];
__device__ unsigned int g_hist[BB * NBINS];
__device__ int          g_topidx[BB * TOPK];
__device__ float        g_topscore[BB * TOPK];
__device__ float4       g_sbox[BB * TOPK];
__device__ uint2        g_saux[BB * TOPK];
__device__ int          g_cellstart[BB * 257];
__device__ unsigned int g_mask[BB * TOPK * 32];
__device__ unsigned int g_wnz[BB * TOPK];

// ---------------- K1: WIDE score + histogram (HBM-floor read) ----------------
__global__ __launch_bounds__(256) void k_score(const float* __restrict__ x) {
    int b = blockIdx.y;
#pragma unroll
    for (int a = 0; a < 4; ++a) {
        int n = blockIdx.x * 1024 + a * 256 + threadIdx.x;
        if (n < NN) {
            const float4* row = (const float4*)(x + (long)(b * NN + n) * 16);
            float s = row[1].x * row[3].w;
            g_scores[b * NN + n] = s;
            if (s > CONF) {
                int bin = min((int)((s - CONF) * (1024.0f / 0.75f)), NBINS - 1);
                atomicAdd(&g_hist[b * NBINS + bin], 1u);
            }
        }
    }
}

// ---------------- K2: threshold + compact + hybrid-bitonic(2048) + bin ------
__global__ __launch_bounds__(1024) void k_topk(const float* __restrict__ x) {
    __shared__ unsigned long long sk[CAP];
    __shared__ int sT, wcnt[32], woff[32];
    __shared__ unsigned int wtot[32], wexc[32];
    __shared__ int counts[256], scanbuf[256], cstart[257];

    int b = blockIdx.x, t = threadIdx.x;
    int w = t >> 5, lane = t & 31;

    // ---- threshold: shfl-based suffix scan of histogram (2 barriers) ----
    unsigned int v = g_hist[b * NBINS + t];
    g_hist[b * NBINS + t] = 0u;          // replay-safe reset
    if (t == 0) sT = 0;
    unsigned int s = v;                  // suffix within warp: sum of bins [t..32w+31]
#pragma unroll
    for (int off = 1; off < 32; off <<= 1) {
        unsigned int y = __shfl_down_sync(0xffffffffu, s, off);
        if (lane + off < 32) s += y;
    }
    if (lane == 0) wtot[w] = s;          // warp total = suffix at lane 0
    __syncthreads();
    if (t < 32) {
        unsigned int q = wtot[t];
        unsigned int qs = q;
#pragma unroll
        for (int off = 1; off < 32; off <<= 1) {
            unsigned int y = __shfl_down_sync(0xffffffffu, qs, off);
            if (t + off < 32) qs += y;
        }
        wexc[t] = qs - q;                // sum of warp totals AFTER warp t
    }
    __syncthreads();
    unsigned int suf = s + wexc[w];      // sum of bins [t..1023]
    if (suf >= TOPK) atomicMax(&sT, t);
    sk[t] = 0ULL; sk[t + 1024] = 0ULL;
    __syncthreads();

    // ---- compact pass 1: per-warp count ----
    int T = sT;
    int base = w * CHUNK;
    int lim = min(base + CHUNK, NN);
    {
        int cnt = 0;
        for (int it = 0; it < 25; ++it) {
            int n = base + it * 32 + lane;
            bool sel = false;
            if (n < lim) {
                float sc = g_scores[b * NN + n];
                if (sc > CONF) {
                    int bin = min((int)((sc - CONF) * (1024.0f / 0.75f)), NBINS - 1);
                    sel = (bin >= T);
                }
            }
            cnt += __popc(__ballot_sync(0xffffffffu, sel));
        }
        if (lane == 0) wcnt[w] = cnt;
    }
    __syncthreads();
    if (t < 32) {
        int vv = wcnt[t], p = vv;
#pragma unroll
        for (int off = 1; off < 32; off <<= 1) {
            int y = __shfl_up_sync(0xffffffffu, p, off);
            if (t >= off) p += y;
        }
        woff[t] = p - vv;
    }
    __syncthreads();
    // ---- compact pass 2: write at exact offsets ----
    {
        int off = woff[w];
        int run = 0;
        for (int it = 0; it < 25; ++it) {
            int n = base + it * 32 + lane;
            bool sel = false;
            float sc = 0.0f;
            if (n < lim) {
                sc = g_scores[b * NN + n];
                if (sc > CONF) {
                    int bin = min((int)((sc - CONF) * (1024.0f / 0.75f)), NBINS - 1);
                    sel = (bin >= T);
                }
            }
            unsigned int m = __ballot_sync(0xffffffffu, sel);
            if (sel) {
                int pos = off + run + __popc(m & ((1u << lane) - 1u));
                if (pos < CAP) {
                    sk[pos] = ((unsigned long long)__float_as_uint(sc) << 32) |
                              (unsigned long long)(0xFFFFFFFFu - (unsigned)n);
                }
            }
            run += __popc(m);
        }
    }
    __syncthreads();

    // ---- hybrid bitonic sort desc (2048 u64): shfl for j<=32, smem j>=64 ----
    {
        int w64 = w << 6;
        int ia = w64 + lane, ic = ia + 32;
        unsigned long long a = sk[ia], c = sk[ic];
        // stages k=2..32: pure shfl butterflies
#pragma unroll
        for (int k = 2; k <= 32; k <<= 1) {
#pragma unroll
            for (int j = 16; j >= 1; j >>= 1) {
                if (j < k) {
                    {
                        unsigned long long o = __shfl_xor_sync(0xffffffffu, a, j);
                        bool keepMax = (((ia & j) == 0) == ((ia & k) == 0));
                        a = keepMax ? (a > o ? a : o) : (a < o ? a : o);
                    }
                    {
                        unsigned long long o = __shfl_xor_sync(0xffffffffu, c, j);
                        bool keepMax = (((ic & j) == 0) == ((ic & k) == 0));
                        c = keepMax ? (c > o ? c : o) : (c < o ? c : o);
                    }
                }
            }
        }
        // stage k=64: j=32 in-thread, then j=16..1 shfl
        {
            bool desc = ((ia & 64) == 0);
            unsigned long long hi = a > c ? a : c, lo = a > c ? c : a;
            a = desc ? hi : lo; c = desc ? lo : hi;
#pragma unroll
            for (int j = 16; j >= 1; j >>= 1) {
                {
                    unsigned long long o = __shfl_xor_sync(0xffffffffu, a, j);
                    bool keepMax = (((ia & j) == 0) == desc);
                    a = keepMax ? (a > o ? a : o) : (a < o ? a : o);
                }
                {
                    unsigned long long o = __shfl_xor_sync(0xffffffffu, c, j);
                    bool keepMax = (((ic & j) == 0) == desc);
                    c = keepMax ? (c > o ? c : o) : (c < o ? c : o);
                }
            }
        }
        sk[ia] = a; sk[ic] = c;
    }
    __syncthreads();
    // stages k=128..2048: smem passes for j>=64, register session for j<=32
    for (int k = 128; k <= CAP; k <<= 1) {
        for (int j = k >> 1; j >= 64; j >>= 1) {
#pragma unroll
            for (int ee = 0; ee < 2; ++ee) {
                int e = t + ee * 1024;
                int ixj = e ^ j;
                if (ixj > e) {
                    unsigned long long a = sk[e], c = sk[ixj];
                    bool desc = ((e & k) == 0);
                    if (desc ? (a < c) : (a > c)) { sk[e] = c; sk[ixj] = a; }
                }
            }
            __syncthreads();
        }
        {
            int w64 = w << 6;
            int ia = w64 + lane, ic = ia + 32;
            unsigned long long a = sk[ia], c = sk[ic];
            bool desc = ((ia & k) == 0);   // uniform over the 64-block (k>=128)
            unsigned long long hi = a > c ? a : c, lo = a > c ? c : a;
            a = desc ? hi : lo; c = desc ? lo : hi;
#pragma unroll
            for (int j = 16; j >= 1; j >>= 1) {
                {
                    unsigned long long o = __shfl_xor_sync(0xffffffffu, a, j);
                    bool keepMax = (((ia & j) == 0) == desc);
                    a = keepMax ? (a > o ? a : o) : (a < o ? a : o);
                }
                {
                    unsigned long long o = __shfl_xor_sync(0xffffffffu, c, j);
                    bool keepMax = (((ic & j) == 0) == desc);
                    c = keepMax ? (c > o ? c : o) : (c < o ? c : o);
                }
            }
            sk[ia] = a; sk[ic] = c;
        }
        __syncthreads();
    }

    // ---- extract top-1024, gather boxes ----
    unsigned long long key = sk[t];
    float sc = __uint_as_float((unsigned)(key >> 32));
    int idx = (key == 0ULL) ? 0 : (int)(0xFFFFFFFFu - (unsigned)(key & 0xFFFFFFFFu));
    if (idx < 0 || idx >= NN) idx = 0;
    g_topscore[b * TOPK + t] = (key == 0ULL) ? 0.0f : sc;
    g_topidx[b * TOPK + t] = idx;
    const float4* row = (const float4*)(x + (long)(b * NN + idx) * 16);
    float4 c0 = row[0];
    float hw = c0.z * 0.5f, hh = c0.w * 0.5f;
    float4 box = make_float4(c0.x - hw, c0.y - hh, c0.x + hw, c0.y + hh);
    float sv = 0.45f * (fmaxf(box.z - box.x, 0.0f) * fmaxf(box.w - box.y, 0.0f));
    int cellx = min(15, max(0, (int)(c0.x * 0.025f)));
    int celly = min(15, max(0, (int)(c0.y * 0.025f)));
    int cell = celly * 16 + cellx;

    // ---- spatial binning ----
    if (t < 256) counts[t] = 0;
    __syncthreads();
    atomicAdd(&counts[cell], 1);
    __syncthreads();
    if (t < 256) scanbuf[t] = counts[t];
    __syncthreads();
    for (int off = 1; off < 256; off <<= 1) {
        int add = 0;
        if (t < 256 && t >= off) add = scanbuf[t - off];
        __syncthreads();
        if (t < 256) scanbuf[t] += add;
        __syncthreads();
    }
    if (t == 0) cstart[0] = 0;
    if (t < 256) { cstart[t + 1] = scanbuf[t]; counts[t] = (t == 0) ? 0 : scanbuf[t - 1]; }
    __syncthreads();
    {
        int pos = atomicAdd(&counts[cell], 1);
        g_sbox[b * TOPK + pos] = box;
        g_saux[b * TOPK + pos] = make_uint2(__float_as_uint(sv), (unsigned)t);
    }
    if (t < 257) g_cellstart[b * 257 + t] = cstart[t];
}

// ---------------- K3: sparse suppression-mask, 4 threads per entry ----------
__global__ __launch_bounds__(512) void k_pairs() {
    __shared__ float4       sbox[TOPK];     // 16KB
    __shared__ uint2        sax[TOPK];      // 8KB
    __shared__ int          cs[257];        // 1KB
    __shared__ unsigned int rows[128 * 33]; // 16.5KB

    int b = blockIdx.y, t = threadIdx.x;
    int le = t >> 2;                  // local entry 0..127
    int q  = t & 3;                   // quarter
    int s  = blockIdx.x * 128 + le;   // global spatial entry

    for (int e = t; e < TOPK; e += 512) {
        sbox[e] = g_sbox[b * TOPK + e];
        sax[e]  = g_saux[b * TOPK + e];
    }
    for (int e = t; e < 257; e += 512) cs[e] = g_cellstart[b * 257 + e];
    __syncthreads();

    unsigned int* rowp = &rows[le * 33];
    for (int ww = q; ww < 32; ww += 4) rowp[ww] = 0u;
    __syncwarp();

    float4 bs = sbox[s];
    uint2 axs = sax[s];
    float u = __uint_as_float(axs.x);
    int rs = (int)axs.y;

    int cl = max(0, (int)((bs.x - 64.5f) * 0.025f));
    int cr = min(15, (int)((bs.z + 64.5f) * 0.025f));
    int ct = max(0, (int)((bs.y - 64.5f) * 0.025f));
    int cb = min(15, (int)((bs.w + 64.5f) * 0.025f));

    for (int cy = ct; cy <= cb; ++cy) {
        int e0 = cs[cy * 16 + cl];
        int e1 = cs[cy * 16 + cr + 1];
#pragma unroll 2
        for (int e = e0 + q; e < e1; e += 4) {
            float4 be = sbox[e];
            uint2 axe = sax[e];
            float ix1 = fmaxf(bs.x, be.x), iy1 = fmaxf(bs.y, be.y);
            float ix2 = fminf(bs.z, be.z), iy2 = fminf(bs.w, be.w);
            float inter = fmaxf(ix2 - ix1, 0.0f) * fmaxf(iy2 - iy1, 0.0f);
            float sden = u + __uint_as_float(axe.x);
            float diff = fmaf(1.45f, inter, -sden);
            bool bit;
            if (fabsf(diff) <= 2e-5f * sden) {   // rare: exact IEEE path
                float ai = fmaxf(bs.z - bs.x, 0.0f) * fmaxf(bs.w - bs.y, 0.0f);
                float aj = fmaxf(be.z - be.x, 0.0f) * fmaxf(be.w - be.y, 0.0f);
                float den = (ai + aj - inter) + 1e-9f;
                bit = (__fdiv_rn(inter, den) > IOUT);
            } else {
                bit = (diff > 0.0f);
            }
            int re = (int)axe.y;
            if (bit && re > rs) atomicOr(&rowp[re >> 5], 1u << (re & 31));
        }
    }
    __syncwarp();

    if (q == 0) {
        unsigned int wm = 0u;
#pragma unroll
        for (int ww = 0; ww < 32; ++ww) wm |= (rowp[ww] != 0u) ? (1u << ww) : 0u;
        g_wnz[b * TOPK + rs] = wm;
        if (wm) {
            unsigned int* orow = &g_mask[((long)(b * TOPK + rs)) * 32];
#pragma unroll
            for (int ww = 0; ww < 32; ++ww) orow[ww] = rowp[ww];
        }
    }
}

// ---------------- K4: rank-indexed sparse greedy scan + output ----------------
__global__ __launch_bounds__(1024) void k_scan_out(const float* __restrict__ x,
                                                   float* __restrict__ out) {
    extern __shared__ unsigned int srow[];          // [TOPK * RSTR]
    __shared__ unsigned int validw[32];
    __shared__ unsigned int harw[32];
    __shared__ unsigned int keepw[32];

    int b = blockIdx.x, t = threadIdx.x;
    int w = t >> 5, lane = t & 31;

    float sc = g_topscore[b * TOPK + t];
    unsigned int vb = __ballot_sync(0xffffffffu, sc > 0.0f);
    if (lane == 0) validw[w] = vb;

    bool nzf = (g_wnz[b * TOPK + t] != 0u);
    unsigned int hb = __ballot_sync(0xffffffffu, nzf);
    if (lane == 0) harw[w] = hb;

    if (nzf) {
        const uint4* src = (const uint4*)&g_mask[((long)(b * TOPK + t)) * 32];
        uint4* dst = (uint4*)&srow[t * RSTR];
#pragma unroll
        for (int i = 0; i < 8; ++i) dst[i] = src[i];
    }
    __syncthreads();

    if (t < 32) {
        unsigned int removed = 0u;
        unsigned int vwl = validw[lane];
        for (int wi = 0; wi < 32; ++wi) {
            unsigned int alive = __shfl_sync(0xffffffffu, vwl & ~removed, wi);
            unsigned int evt = alive & harw[wi];               // uniform LDS
            while (evt) {
                int j = __ffs(evt) - 1;                        // warp-uniform
                evt &= evt - 1u;
                int rbase = ((wi << 5) + j) * RSTR;
                unsigned int rw = srow[rbase + lane];          // per-lane LDS
                unsigned int au = srow[rbase + wi];            // uniform LDS broadcast
                removed |= rw;
                alive &= ~au;
                evt &= alive;
            }
            if (lane == 0) keepw[wi] = alive;
        }
    }
    __syncthreads();

    unsigned int kept = (keepw[t >> 5] >> (t & 31)) & 1u;
    float4* orow = (float4*)(out + (long)(b * TOPK + t) * 16);
    if (kept) {
        int idx = g_topidx[b * TOPK + t];
        const float4* row = (const float4*)(x + (long)(b * NN + idx) * 16);
        float4 c0 = row[0], c1 = row[1], c2 = row[2], c3 = row[3];
        float hw = c0.z * 0.5f, hh = c0.w * 0.5f;
        orow[0] = make_float4(c0.x - hw, c0.y - hh, c0.x + hw, c0.y + hh);
        orow[1] = make_float4(sc, c1.y, c1.z, c1.w);
        orow[2] = c2;
        orow[3] = make_float4(c3.x, c3.y, c3.z, 0.0f);
    } else {
        float4 z = make_float4(0.0f, 0.0f, 0.0f, 0.0f);
        orow[0] = z; orow[1] = z; orow[2] = z; orow[3] = z;
    }
}

// ---------------- launch ----------------
extern "C" void kernel_launch(void* const* d_in, const int* in_sizes, int n_in,
                              void* d_out, int out_size) {
    const float* x = (const float*)d_in[0];
    float* out = (float*)d_out;
    (void)in_sizes; (void)n_in; (void)out_size;

    const int scan_smem = TOPK * RSTR * 4;   // 147456 bytes
    cudaFuncSetAttribute(k_scan_out, cudaFuncAttributeMaxDynamicSharedMemorySize, scan_smem);

    {
        dim3 g((NN + 1023) / 1024, BB);
        k_score<<<g, 256>>>(x);
    }
    k_topk<<<BB, 1024>>>(x);
    {
        dim3 g(8, BB);
        k_pairs<<<g, 512>>>();
    }
    k_scan_out<<<BB, 1024, scan_smem>>>(x, out);
}

// round 15
// speedup vs baseline: 1.2472x; 1.0161x over previous
#include <cuda_runtime.h>
#include <cuda_bf16.h>

#define BB    64
#define NN    25200
#define TOPK  1024
#define CAP   2048
#define NBINS 1024
#define CONF  0.25f
#define IOUT  0.45f
#define CHUNK 788          // ceil(25200/32)
#define RSTR  36           // srow stride (words): conflict-free + 16B aligned

// ---------------- scratch (device globals: allocation-free) ----------------
__device__ float        g_scores[BB * NN];
__device__ unsigned int g_hist[BB * NBINS];
__device__ int          g_topidx[BB * TOPK];
__device__ float        g_topscore[BB * TOPK];
__device__ float4       g_sbox[BB * TOPK];
__device__ uint2        g_saux[BB * TOPK];
__device__ int          g_cellstart[BB * 257];
__device__ unsigned int g_mask[BB * TOPK * 32];
__device__ unsigned int g_wnz[BB * TOPK];
__device__ unsigned int g_keep[BB * 32];

// ---------------- K1: WIDE score + histogram (HBM-floor read) ----------------
__global__ __launch_bounds__(256) void k_score(const float* __restrict__ x) {
    int b = blockIdx.y;
#pragma unroll
    for (int a = 0; a < 4; ++a) {
        int n = blockIdx.x * 1024 + a * 256 + threadIdx.x;
        if (n < NN) {
            const float4* row = (const float4*)(x + (long)(b * NN + n) * 16);
            float s = row[1].x * row[3].w;
            g_scores[b * NN + n] = s;
            if (s > CONF) {
                int bin = min((int)((s - CONF) * (1024.0f / 0.75f)), NBINS - 1);
                atomicAdd(&g_hist[b * NBINS + bin], 1u);
            }
        }
    }
}

// ---------------- K2: threshold + 1-read compact + hybrid-bitonic + bin -----
__global__ __launch_bounds__(1024) void k_topk(const float* __restrict__ x) {
    __shared__ unsigned long long sk[CAP];
    __shared__ int sT, wcnt[32], woff[32];
    __shared__ unsigned int wtot[32], wexc[32];
    __shared__ int counts[256], scanbuf[256], cstart[257];

    int b = blockIdx.x, t = threadIdx.x;
    int w = t >> 5, lane = t & 31;

    // ---- threshold: shfl-based suffix scan of histogram (2 barriers) ----
    unsigned int v = g_hist[b * NBINS + t];
    g_hist[b * NBINS + t] = 0u;          // replay-safe reset
    if (t == 0) sT = 0;
    unsigned int s = v;
#pragma unroll
    for (int off = 1; off < 32; off <<= 1) {
        unsigned int y = __shfl_down_sync(0xffffffffu, s, off);
        if (lane + off < 32) s += y;
    }
    if (lane == 0) wtot[w] = s;
    __syncthreads();
    if (t < 32) {
        unsigned int q = wtot[t];
        unsigned int qs = q;
#pragma unroll
        for (int off = 1; off < 32; off <<= 1) {
            unsigned int y = __shfl_down_sync(0xffffffffu, qs, off);
            if (t + off < 32) qs += y;
        }
        wexc[t] = qs - q;
    }
    __syncthreads();
    unsigned int suf = s + wexc[w];
    if (suf >= TOPK) atomicMax(&sT, t);
    sk[t] = 0ULL; sk[t + 1024] = 0ULL;
    __syncthreads();

    // ---- compact pass 1: count + record sel bits (single global read) ----
    int T = sT;
    int base = w * CHUNK;
    int lim = min(base + CHUNK, NN);
    unsigned int selbits = 0u;
    {
        int cnt = 0;
        for (int it = 0; it < 25; ++it) {
            int n = base + it * 32 + lane;
            bool sel = false;
            if (n < lim) {
                float sc = g_scores[b * NN + n];
                if (sc > CONF) {
                    int bin = min((int)((sc - CONF) * (1024.0f / 0.75f)), NBINS - 1);
                    sel = (bin >= T);
                }
            }
            selbits |= sel ? (1u << it) : 0u;
            cnt += __popc(__ballot_sync(0xffffffffu, sel));
        }
        if (lane == 0) wcnt[w] = cnt;
    }
    __syncthreads();
    if (t < 32) {
        int vv = wcnt[t], p = vv;
#pragma unroll
        for (int off = 1; off < 32; off <<= 1) {
            int y = __shfl_up_sync(0xffffffffu, p, off);
            if (t >= off) p += y;
        }
        woff[t] = p - vv;
    }
    __syncthreads();
    // ---- compact pass 2: replay bitmask; reload score only when selected ----
    {
        int off = woff[w];
        int run = 0;
        for (int it = 0; it < 25; ++it) {
            bool sel = (selbits >> it) & 1u;
            unsigned int m = __ballot_sync(0xffffffffu, sel);
            if (sel) {
                int n = base + it * 32 + lane;
                float sc = g_scores[b * NN + n];   // L1-hot
                int pos = off + run + __popc(m & ((1u << lane) - 1u));
                if (pos < CAP) {
                    sk[pos] = ((unsigned long long)__float_as_uint(sc) << 32) |
                              (unsigned long long)(0xFFFFFFFFu - (unsigned)n);
                }
            }
            run += __popc(m);
        }
    }
    __syncthreads();

    // ---- hybrid bitonic sort desc (2048 u64): shfl j<=32, smem j>=64 ----
    {
        int w64 = w << 6;
        int ia = w64 + lane, ic = ia + 32;
        unsigned long long a = sk[ia], c = sk[ic];
#pragma unroll
        for (int k = 2; k <= 32; k <<= 1) {
#pragma unroll
            for (int j = 16; j >= 1; j >>= 1) {
                if (j < k) {
                    {
                        unsigned long long o = __shfl_xor_sync(0xffffffffu, a, j);
                        bool keepMax = (((ia & j) == 0) == ((ia & k) == 0));
                        a = keepMax ? (a > o ? a : o) : (a < o ? a : o);
                    }
                    {
                        unsigned long long o = __shfl_xor_sync(0xffffffffu, c, j);
                        bool keepMax = (((ic & j) == 0) == ((ic & k) == 0));
                        c = keepMax ? (c > o ? c : o) : (c < o ? c : o);
                    }
                }
            }
        }
        {
            bool desc = ((ia & 64) == 0);
            unsigned long long hi = a > c ? a : c, lo = a > c ? c : a;
            a = desc ? hi : lo; c = desc ? lo : hi;
#pragma unroll
            for (int j = 16; j >= 1; j >>= 1) {
                {
                    unsigned long long o = __shfl_xor_sync(0xffffffffu, a, j);
                    bool keepMax = (((ia & j) == 0) == desc);
                    a = keepMax ? (a > o ? a : o) : (a < o ? a : o);
                }
                {
                    unsigned long long o = __shfl_xor_sync(0xffffffffu, c, j);
                    bool keepMax = (((ic & j) == 0) == desc);
                    c = keepMax ? (c > o ? c : o) : (c < o ? c : o);
                }
            }
        }
        sk[ia] = a; sk[ic] = c;
    }
    __syncthreads();
    for (int k = 128; k <= CAP; k <<= 1) {
        for (int j = k >> 1; j >= 64; j >>= 1) {
#pragma unroll
            for (int ee = 0; ee < 2; ++ee) {
                int e = t + ee * 1024;
                int ixj = e ^ j;
                if (ixj > e) {
                    unsigned long long a = sk[e], c = sk[ixj];
                    bool desc = ((e & k) == 0);
                    if (desc ? (a < c) : (a > c)) { sk[e] = c; sk[ixj] = a; }
                }
            }
            __syncthreads();
        }
        {
            int w64 = w << 6;
            int ia = w64 + lane, ic = ia + 32;
            unsigned long long a = sk[ia], c = sk[ic];
            bool desc = ((ia & k) == 0);
            unsigned long long hi = a > c ? a : c, lo = a > c ? c : a;
            a = desc ? hi : lo; c = desc ? lo : hi;
#pragma unroll
            for (int j = 16; j >= 1; j >>= 1) {
                {
                    unsigned long long o = __shfl_xor_sync(0xffffffffu, a, j);
                    bool keepMax = (((ia & j) == 0) == desc);
                    a = keepMax ? (a > o ? a : o) : (a < o ? a : o);
                }
                {
                    unsigned long long o = __shfl_xor_sync(0xffffffffu, c, j);
                    bool keepMax = (((ic & j) == 0) == desc);
                    c = keepMax ? (c > o ? c : o) : (c < o ? c : o);
                }
            }
            sk[ia] = a; sk[ic] = c;
        }
        __syncthreads();
    }

    // ---- extract top-1024, gather boxes ----
    unsigned long long key = sk[t];
    float sc = __uint_as_float((unsigned)(key >> 32));
    int idx = (key == 0ULL) ? 0 : (int)(0xFFFFFFFFu - (unsigned)(key & 0xFFFFFFFFu));
    if (idx < 0 || idx >= NN) idx = 0;
    g_topscore[b * TOPK + t] = (key == 0ULL) ? 0.0f : sc;
    g_topidx[b * TOPK + t] = idx;
    const float4* row = (const float4*)(x + (long)(b * NN + idx) * 16);
    float4 c0 = row[0];
    float hw = c0.z * 0.5f, hh = c0.w * 0.5f;
    float4 box = make_float4(c0.x - hw, c0.y - hh, c0.x + hw, c0.y + hh);
    float sv = 0.45f * (fmaxf(box.z - box.x, 0.0f) * fmaxf(box.w - box.y, 0.0f));
    int cellx = min(15, max(0, (int)(c0.x * 0.025f)));
    int celly = min(15, max(0, (int)(c0.y * 0.025f)));
    int cell = celly * 16 + cellx;

    if (t < 256) counts[t] = 0;
    __syncthreads();
    atomicAdd(&counts[cell], 1);
    __syncthreads();
    if (t < 256) scanbuf[t] = counts[t];
    __syncthreads();
    for (int off = 1; off < 256; off <<= 1) {
        int add = 0;
        if (t < 256 && t >= off) add = scanbuf[t - off];
        __syncthreads();
        if (t < 256) scanbuf[t] += add;
        __syncthreads();
    }
    if (t == 0) cstart[0] = 0;
    if (t < 256) { cstart[t + 1] = scanbuf[t]; counts[t] = (t == 0) ? 0 : scanbuf[t - 1]; }
    __syncthreads();
    {
        int pos = atomicAdd(&counts[cell], 1);
        g_sbox[b * TOPK + pos] = box;
        g_saux[b * TOPK + pos] = make_uint2(__float_as_uint(sv), (unsigned)t);
    }
    if (t < 257) g_cellstart[b * 257 + t] = cstart[t];
}

// ---------------- K3: sparse suppression-mask, 8 threads per entry ----------
__global__ __launch_bounds__(1024) void k_pairs() {
    __shared__ float4       sbox[TOPK];     // 16KB
    __shared__ uint2        sax[TOPK];      // 8KB
    __shared__ int          cs[257];        // 1KB
    __shared__ unsigned int rows[128 * 33]; // 16.5KB

    int b = blockIdx.y, t = threadIdx.x;
    int le = t >> 3;                  // local entry 0..127
    int q  = t & 7;                   // eighth
    int s  = blockIdx.x * 128 + le;   // global spatial entry

    for (int e = t; e < TOPK; e += 1024) {
        sbox[e] = g_sbox[b * TOPK + e];
        sax[e]  = g_saux[b * TOPK + e];
    }
    for (int e = t; e < 257; e += 1024) cs[e] = g_cellstart[b * 257 + e];
    __syncthreads();

    unsigned int* rowp = &rows[le * 33];
    for (int ww = q; ww < 32; ww += 8) rowp[ww] = 0u;
    __syncwarp();

    float4 bs = sbox[s];
    uint2 axs = sax[s];
    float u = __uint_as_float(axs.x);
    int rs = (int)axs.y;

    int cl = max(0, (int)((bs.x - 64.5f) * 0.025f));
    int cr = min(15, (int)((bs.z + 64.5f) * 0.025f));
    int ct = max(0, (int)((bs.y - 64.5f) * 0.025f));
    int cb = min(15, (int)((bs.w + 64.5f) * 0.025f));

    for (int cy = ct; cy <= cb; ++cy) {
        int e0 = cs[cy * 16 + cl];
        int e1 = cs[cy * 16 + cr + 1];
#pragma unroll 2
        for (int e = e0 + q; e < e1; e += 8) {
            float4 be = sbox[e];
            uint2 axe = sax[e];
            float ix1 = fmaxf(bs.x, be.x), iy1 = fmaxf(bs.y, be.y);
            float ix2 = fminf(bs.z, be.z), iy2 = fminf(bs.w, be.w);
            float inter = fmaxf(ix2 - ix1, 0.0f) * fmaxf(iy2 - iy1, 0.0f);
            float sden = u + __uint_as_float(axe.x);
            float diff = fmaf(1.45f, inter, -sden);
            bool bit;
            if (fabsf(diff) <= 2e-5f * sden) {   // rare: exact IEEE path
                float ai = fmaxf(bs.z - bs.x, 0.0f) * fmaxf(bs.w - bs.y, 0.0f);
                float aj = fmaxf(be.z - be.x, 0.0f) * fmaxf(be.w - be.y, 0.0f);
                float den = (ai + aj - inter) + 1e-9f;
                bit = (__fdiv_rn(inter, den) > IOUT);
            } else {
                bit = (diff > 0.0f);
            }
            int re = (int)axe.y;
            if (bit && re > rs) atomicOr(&rowp[re >> 5], 1u << (re & 31));
        }
    }
    __syncwarp();

    if (q == 0) {
        unsigned int wm = 0u;
#pragma unroll
        for (int ww = 0; ww < 32; ++ww) wm |= (rowp[ww] != 0u) ? (1u << ww) : 0u;
        g_wnz[b * TOPK + rs] = wm;
        if (wm) {
            unsigned int* orow = &g_mask[((long)(b * TOPK + rs)) * 32];
#pragma unroll
            for (int ww = 0; ww < 32; ++ww) orow[ww] = rowp[ww];
        }
    }
}

// ---------------- K4: rank-indexed sparse greedy scan -> g_keep ----------------
__global__ __launch_bounds__(1024) void k_scan() {
    extern __shared__ unsigned int srow[];          // [TOPK * RSTR]
    __shared__ unsigned int validw[32];
    __shared__ unsigned int harw[32];

    int b = blockIdx.x, t = threadIdx.x;
    int w = t >> 5, lane = t & 31;

    float sc = g_topscore[b * TOPK + t];
    unsigned int vb = __ballot_sync(0xffffffffu, sc > 0.0f);
    if (lane == 0) validw[w] = vb;

    bool nzf = (g_wnz[b * TOPK + t] != 0u);
    unsigned int hb = __ballot_sync(0xffffffffu, nzf);
    if (lane == 0) harw[w] = hb;

    if (nzf) {
        const uint4* src = (const uint4*)&g_mask[((long)(b * TOPK + t)) * 32];
        uint4* dst = (uint4*)&srow[t * RSTR];
#pragma unroll
        for (int i = 0; i < 8; ++i) dst[i] = src[i];
    }
    __syncthreads();

    if (t < 32) {
        unsigned int removed = 0u;
        unsigned int vwl = validw[lane];
        for (int wi = 0; wi < 32; ++wi) {
            unsigned int alive = __shfl_sync(0xffffffffu, vwl & ~removed, wi);
            unsigned int evt = alive & harw[wi];               // uniform LDS
            while (evt) {
                int j = __ffs(evt) - 1;                        // warp-uniform
                evt &= evt - 1u;
                int rbase = ((wi << 5) + j) * RSTR;
                unsigned int rw = srow[rbase + lane];          // per-lane LDS
                unsigned int au = srow[rbase + wi];            // uniform LDS broadcast
                removed |= rw;
                alive &= ~au;
                evt &= alive;
            }
            g_keep[b * 32 + wi] = alive;   // all lanes same value? no: write lane 0
        }
    }
}

// ---------------- K5: WIDE output gather/write ----------------
__global__ __launch_bounds__(128) void k_out(const float* __restrict__ x,
                                             float* __restrict__ out) {
    int b = blockIdx.y;
    int r = blockIdx.x * 128 + threadIdx.x;   // rank
    unsigned int kept = (g_keep[b * 32 + (r >> 5)] >> (r & 31)) & 1u;
    float4* orow = (float4*)(out + (long)(b * TOPK + r) * 16);
    if (kept) {
        int idx = g_topidx[b * TOPK + r];
        float sc = g_topscore[b * TOPK + r];
        const float4* row = (const float4*)(x + (long)(b * NN + idx) * 16);
        float4 c0 = row[0], c1 = row[1], c2 = row[2], c3 = row[3];
        float hw = c0.z * 0.5f, hh = c0.w * 0.5f;
        orow[0] = make_float4(c0.x - hw, c0.y - hh, c0.x + hw, c0.y + hh);
        orow[1] = make_float4(sc, c1.y, c1.z, c1.w);
        orow[2] = c2;
        orow[3] = make_float4(c3.x, c3.y, c3.z, 0.0f);
    } else {
        float4 z = make_float4(0.0f, 0.0f, 0.0f, 0.0f);
        orow[0] = z; orow[1] = z; orow[2] = z; orow[3] = z;
    }
}

// ---------------- launch ----------------
extern "C" void kernel_launch(void* const* d_in, const int* in_sizes, int n_in,
                              void* d_out, int out_size) {
    const float* x = (const float*)d_in[0];
    float* out = (float*)d_out;
    (void)in_sizes; (void)n_in; (void)out_size;

    const int scan_smem = TOPK * RSTR * 4;   // 147456 bytes
    cudaFuncSetAttribute(k_scan, cudaFuncAttributeMaxDynamicSharedMemorySize, scan_smem);

    {
        dim3 g((NN + 1023) / 1024, BB);
        k_score<<<g, 256>>>(x);
    }
    k_topk<<<BB, 1024>>>(x);
    {
        dim3 g(8, BB);
        k_pairs<<<g, 1024>>>();
    }
    k_scan<<<BB, 1024, scan_smem>>>();
    {
        dim3 g(8, BB);
        k_out<<<g, 128>>>(x, out);
    }
}

// round 16
// speedup vs baseline: 1.2780x; 1.0247x over previous
#include <cuda_runtime.h>
#include <cuda_bf16.h>

#define BB    64
#define NN    25200
#define TOPK  1024
#define CAP   2048
#define NB    256          // histogram bins
#define BSCALE (256.0f / 0.75f)
#define CONF  0.25f
#define IOUT  0.45f
#define CHUNK 788          // ceil(25200/32)
#define RSTR  36           // srow stride (words): conflict-free + 16B aligned

// ---------------- scratch (device globals: allocation-free) ----------------
__device__ float        g_scores[BB * NN];
__device__ unsigned int g_hist[BB * NB];
__device__ int          g_topidx[BB * TOPK];
__device__ float        g_topscore[BB * TOPK];
__device__ float4       g_sbox[BB * TOPK];
__device__ uint2        g_saux[BB * TOPK];
__device__ int          g_cellstart[BB * 257];
__device__ unsigned int g_mask[BB * TOPK * 32];
__device__ unsigned int g_wnz[BB * TOPK];

// ---------------- K1: WIDE score + smem histogram ----------------
__global__ __launch_bounds__(256) void k_score(const float* __restrict__ x) {
    __shared__ unsigned int h[NB];
    int b = blockIdx.y, t = threadIdx.x;
    h[t] = 0u;
    __syncthreads();
#pragma unroll
    for (int a = 0; a < 4; ++a) {
        int n = blockIdx.x * 1024 + a * 256 + t;
        if (n < NN) {
            const float4* row = (const float4*)(x + (long)(b * NN + n) * 16);
            float s = row[1].x * row[3].w;
            g_scores[b * NN + n] = s;
            if (s > CONF) {
                int bin = min((int)((s - CONF) * BSCALE), NB - 1);
                atomicAdd(&h[bin], 1u);
            }
        }
    }
    __syncthreads();
    unsigned int c = h[t];
    if (c) atomicAdd(&g_hist[b * NB + t], c);
}

// ---------------- K2: threshold + 1-read compact + hybrid-bitonic + bin -----
__global__ __launch_bounds__(1024) void k_topk(const float* __restrict__ x) {
    __shared__ unsigned long long sk[CAP];
    __shared__ int sT, wcnt[32], woff[32];
    __shared__ unsigned int wtot[8], wexc[8];
    __shared__ int counts[256], scanbuf[256], cstart[257];

    int b = blockIdx.x, t = threadIdx.x;
    int w = t >> 5, lane = t & 31;

    // ---- threshold: shfl suffix scan of 256-bin histogram ----
    if (t == 0) sT = 0;
    unsigned int s = 0u;
    if (t < NB) {
        unsigned int v = g_hist[b * NB + t];
        g_hist[b * NB + t] = 0u;          // replay-safe reset
        s = v;
#pragma unroll
        for (int off = 1; off < 32; off <<= 1) {
            unsigned int y = __shfl_down_sync(0xffffffffu, s, off);
            if (lane + off < 32) s += y;
        }
        if (lane == 0) wtot[w] = s;
    }
    __syncthreads();
    if (t < 8) {
        unsigned int q = wtot[t];
        unsigned int qs = q;
#pragma unroll
        for (int off = 1; off < 8; off <<= 1) {
            unsigned int y = __shfl_down_sync(0x000000ffu, qs, off);
            if (t + off < 8) qs += y;
        }
        wexc[t] = qs - q;
    }
    __syncthreads();
    if (t < NB) {
        unsigned int suf = s + wexc[w];
        if (suf >= TOPK) atomicMax(&sT, t);
    }
    sk[t] = 0ULL; sk[t + 1024] = 0ULL;
    __syncthreads();

    // ---- compact pass 1: count + record sel bits (single global read) ----
    int T = sT;
    int base = w * CHUNK;
    int lim = min(base + CHUNK, NN);
    unsigned int selbits = 0u;
    {
        int cnt = 0;
        for (int it = 0; it < 25; ++it) {
            int n = base + it * 32 + lane;
            bool sel = false;
            if (n < lim) {
                float sc = g_scores[b * NN + n];
                if (sc > CONF) {
                    int bin = min((int)((sc - CONF) * BSCALE), NB - 1);
                    sel = (bin >= T);
                }
            }
            selbits |= sel ? (1u << it) : 0u;
            cnt += __popc(__ballot_sync(0xffffffffu, sel));
        }
        if (lane == 0) wcnt[w] = cnt;
    }
    __syncthreads();
    if (t < 32) {
        int vv = wcnt[t], p = vv;
#pragma unroll
        for (int off = 1; off < 32; off <<= 1) {
            int y = __shfl_up_sync(0xffffffffu, p, off);
            if (t >= off) p += y;
        }
        woff[t] = p - vv;
    }
    __syncthreads();
    // ---- compact pass 2: replay bitmask; reload score only when selected ----
    {
        int off = woff[w];
        int run = 0;
        for (int it = 0; it < 25; ++it) {
            bool sel = (selbits >> it) & 1u;
            unsigned int m = __ballot_sync(0xffffffffu, sel);
            if (sel) {
                int n = base + it * 32 + lane;
                float sc = g_scores[b * NN + n];   // L1-hot
                int pos = off + run + __popc(m & ((1u << lane) - 1u));
                if (pos < CAP) {
                    sk[pos] = ((unsigned long long)__float_as_uint(sc) << 32) |
                              (unsigned long long)(0xFFFFFFFFu - (unsigned)n);
                }
            }
            run += __popc(m);
        }
    }
    __syncthreads();

    // ---- hybrid bitonic sort desc (2048 u64): shfl j<=32, smem j>=64 ----
    {
        int w64 = w << 6;
        int ia = w64 + lane, ic = ia + 32;
        unsigned long long a = sk[ia], c = sk[ic];
#pragma unroll
        for (int k = 2; k <= 32; k <<= 1) {
#pragma unroll
            for (int j = 16; j >= 1; j >>= 1) {
                if (j < k) {
                    {
                        unsigned long long o = __shfl_xor_sync(0xffffffffu, a, j);
                        bool keepMax = (((ia & j) == 0) == ((ia & k) == 0));
                        a = keepMax ? (a > o ? a : o) : (a < o ? a : o);
                    }
                    {
                        unsigned long long o = __shfl_xor_sync(0xffffffffu, c, j);
                        bool keepMax = (((ic & j) == 0) == ((ic & k) == 0));
                        c = keepMax ? (c > o ? c : o) : (c < o ? c : o);
                    }
                }
            }
        }
        {
            bool desc = ((ia & 64) == 0);
            unsigned long long hi = a > c ? a : c, lo = a > c ? c : a;
            a = desc ? hi : lo; c = desc ? lo : hi;
#pragma unroll
            for (int j = 16; j >= 1; j >>= 1) {
                {
                    unsigned long long o = __shfl_xor_sync(0xffffffffu, a, j);
                    bool keepMax = (((ia & j) == 0) == desc);
                    a = keepMax ? (a > o ? a : o) : (a < o ? a : o);
                }
                {
                    unsigned long long o = __shfl_xor_sync(0xffffffffu, c, j);
                    bool keepMax = (((ic & j) == 0) == desc);
                    c = keepMax ? (c > o ? c : o) : (c < o ? c : o);
                }
            }
        }
        sk[ia] = a; sk[ic] = c;
    }
    __syncthreads();
    for (int k = 128; k <= CAP; k <<= 1) {
        for (int j = k >> 1; j >= 64; j >>= 1) {
#pragma unroll
            for (int ee = 0; ee < 2; ++ee) {
                int e = t + ee * 1024;
                int ixj = e ^ j;
                if (ixj > e) {
                    unsigned long long a = sk[e], c = sk[ixj];
                    bool desc = ((e & k) == 0);
                    if (desc ? (a < c) : (a > c)) { sk[e] = c; sk[ixj] = a; }
                }
            }
            __syncthreads();
        }
        {
            int w64 = w << 6;
            int ia = w64 + lane, ic = ia + 32;
            unsigned long long a = sk[ia], c = sk[ic];
            bool desc = ((ia & k) == 0);
            unsigned long long hi = a > c ? a : c, lo = a > c ? c : a;
            a = desc ? hi : lo; c = desc ? lo : hi;
#pragma unroll
            for (int j = 16; j >= 1; j >>= 1) {
                {
                    unsigned long long o = __shfl_xor_sync(0xffffffffu, a, j);
                    bool keepMax = (((ia & j) == 0) == desc);
                    a = keepMax ? (a > o ? a : o) : (a < o ? a : o);
                }
                {
                    unsigned long long o = __shfl_xor_sync(0xffffffffu, c, j);
                    bool keepMax = (((ic & j) == 0) == desc);
                    c = keepMax ? (c > o ? c : o) : (c < o ? c : o);
                }
            }
            sk[ia] = a; sk[ic] = c;
        }
        __syncthreads();
    }

    // ---- extract top-1024, gather boxes ----
    unsigned long long key = sk[t];
    float sc = __uint_as_float((unsigned)(key >> 32));
    int idx = (key == 0ULL) ? 0 : (int)(0xFFFFFFFFu - (unsigned)(key & 0xFFFFFFFFu));
    if (idx < 0 || idx >= NN) idx = 0;
    g_topscore[b * TOPK + t] = (key == 0ULL) ? 0.0f : sc;
    g_topidx[b * TOPK + t] = idx;
    const float4* row = (const float4*)(x + (long)(b * NN + idx) * 16);
    float4 c0 = row[0];
    float hw = c0.z * 0.5f, hh = c0.w * 0.5f;
    float4 box = make_float4(c0.x - hw, c0.y - hh, c0.x + hw, c0.y + hh);
    float sv = 0.45f * (fmaxf(box.z - box.x, 0.0f) * fmaxf(box.w - box.y, 0.0f));
    int cellx = min(15, max(0, (int)(c0.x * 0.025f)));
    int celly = min(15, max(0, (int)(c0.y * 0.025f)));
    int cell = celly * 16 + cellx;

    if (t < 256) counts[t] = 0;
    __syncthreads();
    atomicAdd(&counts[cell], 1);
    __syncthreads();
    if (t < 256) scanbuf[t] = counts[t];
    __syncthreads();
    for (int off = 1; off < 256; off <<= 1) {
        int add = 0;
        if (t < 256 && t >= off) add = scanbuf[t - off];
        __syncthreads();
        if (t < 256) scanbuf[t] += add;
        __syncthreads();
    }
    if (t == 0) cstart[0] = 0;
    if (t < 256) { cstart[t + 1] = scanbuf[t]; counts[t] = (t == 0) ? 0 : scanbuf[t - 1]; }
    __syncthreads();
    {
        int pos = atomicAdd(&counts[cell], 1);
        g_sbox[b * TOPK + pos] = box;
        g_saux[b * TOPK + pos] = make_uint2(__float_as_uint(sv), (unsigned)t);
    }
    if (t < 257) g_cellstart[b * 257 + t] = cstart[t];
}

// ---------------- K3: sparse suppression-mask, 8 threads per entry ----------
__global__ __launch_bounds__(1024) void k_pairs() {
    __shared__ float4       sbox[TOPK];     // 16KB
    __shared__ uint2        sax[TOPK];      // 8KB
    __shared__ int          cs[257];        // 1KB
    __shared__ unsigned int rows[128 * 33]; // 16.5KB

    int b = blockIdx.y, t = threadIdx.x;
    int le = t >> 3;                  // local entry 0..127
    int q  = t & 7;                   // eighth
    int s  = blockIdx.x * 128 + le;   // global spatial entry

    for (int e = t; e < TOPK; e += 1024) {
        sbox[e] = g_sbox[b * TOPK + e];
        sax[e]  = g_saux[b * TOPK + e];
    }
    for (int e = t; e < 257; e += 1024) cs[e] = g_cellstart[b * 257 + e];
    __syncthreads();

    unsigned int* rowp = &rows[le * 33];
    for (int ww = q; ww < 32; ww += 8) rowp[ww] = 0u;
    __syncwarp();

    float4 bs = sbox[s];
    uint2 axs = sax[s];
    float u = __uint_as_float(axs.x);
    int rs = (int)axs.y;

    int cl = max(0, (int)((bs.x - 64.5f) * 0.025f));
    int cr = min(15, (int)((bs.z + 64.5f) * 0.025f));
    int ct = max(0, (int)((bs.y - 64.5f) * 0.025f));
    int cb = min(15, (int)((bs.w + 64.5f) * 0.025f));

    for (int cy = ct; cy <= cb; ++cy) {
        int e0 = cs[cy * 16 + cl];
        int e1 = cs[cy * 16 + cr + 1];
#pragma unroll 2
        for (int e = e0 + q; e < e1; e += 8) {
            float4 be = sbox[e];
            uint2 axe = sax[e];
            float ix1 = fmaxf(bs.x, be.x), iy1 = fmaxf(bs.y, be.y);
            float ix2 = fminf(bs.z, be.z), iy2 = fminf(bs.w, be.w);
            float inter = fmaxf(ix2 - ix1, 0.0f) * fmaxf(iy2 - iy1, 0.0f);
            float sden = u + __uint_as_float(axe.x);
            float diff = fmaf(1.45f, inter, -sden);
            bool bit;
            if (fabsf(diff) <= 2e-5f * sden) {   // rare: exact IEEE path
                float ai = fmaxf(bs.z - bs.x, 0.0f) * fmaxf(bs.w - bs.y, 0.0f);
                float aj = fmaxf(be.z - be.x, 0.0f) * fmaxf(be.w - be.y, 0.0f);
                float den = (ai + aj - inter) + 1e-9f;
                bit = (__fdiv_rn(inter, den) > IOUT);
            } else {
                bit = (diff > 0.0f);
            }
            int re = (int)axe.y;
            if (bit && re > rs) atomicOr(&rowp[re >> 5], 1u << (re & 31));
        }
    }
    __syncwarp();

    if (q == 0) {
        unsigned int wm = 0u;
#pragma unroll
        for (int ww = 0; ww < 32; ++ww) wm |= (rowp[ww] != 0u) ? (1u << ww) : 0u;
        g_wnz[b * TOPK + rs] = wm;
        if (wm) {
            unsigned int* orow = &g_mask[((long)(b * TOPK + rs)) * 32];
#pragma unroll
            for (int ww = 0; ww < 32; ++ww) orow[ww] = rowp[ww];
        }
    }
}

// ---------------- K4: rank-indexed sparse greedy scan + output ----------------
__global__ __launch_bounds__(1024) void k_scan_out(const float* __restrict__ x,
                                                   float* __restrict__ out) {
    extern __shared__ unsigned int srow[];          // [TOPK * RSTR]
    __shared__ unsigned int validw[32];
    __shared__ unsigned int harw[32];
    __shared__ unsigned int keepw[32];

    int b = blockIdx.x, t = threadIdx.x;
    int w = t >> 5, lane = t & 31;

    float sc = g_topscore[b * TOPK + t];
    unsigned int vb = __ballot_sync(0xffffffffu, sc > 0.0f);
    if (lane == 0) validw[w] = vb;

    bool nzf = (g_wnz[b * TOPK + t] != 0u);
    unsigned int hb = __ballot_sync(0xffffffffu, nzf);
    if (lane == 0) harw[w] = hb;

    if (nzf) {
        const uint4* src = (const uint4*)&g_mask[((long)(b * TOPK + t)) * 32];
        uint4* dst = (uint4*)&srow[t * RSTR];
#pragma unroll
        for (int i = 0; i < 8; ++i) dst[i] = src[i];
    }
    __syncthreads();

    if (t < 32) {
        unsigned int removed = 0u;
        unsigned int vwl = validw[lane];
        for (int wi = 0; wi < 32; ++wi) {
            unsigned int alive = __shfl_sync(0xffffffffu, vwl & ~removed, wi);
            unsigned int evt = alive & harw[wi];               // uniform LDS
            while (evt) {
                int j = __ffs(evt) - 1;                        // warp-uniform
                evt &= evt - 1u;
                int rbase = ((wi << 5) + j) * RSTR;
                unsigned int rw = srow[rbase + lane];          // per-lane LDS
                unsigned int au = srow[rbase + wi];            // uniform LDS broadcast
                removed |= rw;
                alive &= ~au;
                evt &= alive;
            }
            if (lane == 0) keepw[wi] = alive;
        }
    }
    __syncthreads();

    unsigned int kept = (keepw[t >> 5] >> (t & 31)) & 1u;
    float4* orow = (float4*)(out + (long)(b * TOPK + t) * 16);
    if (kept) {
        int idx = g_topidx[b * TOPK + t];
        const float4* row = (const float4*)(x + (long)(b * NN + idx) * 16);
        float4 c0 = row[0], c1 = row[1], c2 = row[2], c3 = row[3];
        float hw = c0.z * 0.5f, hh = c0.w * 0.5f;
        orow[0] = make_float4(c0.x - hw, c0.y - hh, c0.x + hw, c0.y + hh);
        orow[1] = make_float4(sc, c1.y, c1.z, c1.w);
        orow[2] = c2;
        orow[3] = make_float4(c3.x, c3.y, c3.z, 0.0f);
    } else {
        float4 z = make_float4(0.0f, 0.0f, 0.0f, 0.0f);
        orow[0] = z; orow[1] = z; orow[2] = z; orow[3] = z;
    }
}

// ---------------- launch ----------------
extern "C" void kernel_launch(void* const* d_in, const int* in_sizes, int n_in,
                              void* d_out, int out_size) {
    const float* x = (const float*)d_in[0];
    float* out = (float*)d_out;
    (void)in_sizes; (void)n_in; (void)out_size;

    const int scan_smem = TOPK * RSTR * 4;   // 147456 bytes
    cudaFuncSetAttribute(k_scan_out, cudaFuncAttributeMaxDynamicSharedMemorySize, scan_smem);

    {
        dim3 g((NN + 1023) / 1024, BB);
        k_score<<<g, 256>>>(x);
    }
    k_topk<<<BB, 1024>>>(x);
    {
        dim3 g(8, BB);
        k_pairs<<<g, 1024>>>();
    }
    k_scan_out<<<BB, 1024, scan_smem>>>(x, out);
}

// round 17
// speedup vs baseline: 1.2808x; 1.0021x over previous
#include <cuda_runtime.h>
#include <cuda_bf16.h>

#define BB    64
#define HB    32           // half batch
#define NN    25200
#define TOPK  1024
#define CAP   2048
#define NB    256
#define BSCALE (256.0f / 0.75f)
#define CONF  0.25f
#define IOUT  0.45f
#define CHUNK 788
#define RSTR  36

// ---------------- scratch (device globals: allocation-free) ----------------
__device__ float        g_scores[BB * NN];
__device__ unsigned int g_hist[BB * NB];
__device__ int          g_topidx[BB * TOPK];
__device__ float        g_topscore[BB * TOPK];
__device__ float4       g_sbox[BB * TOPK];
__device__ uint2        g_saux[BB * TOPK];
__device__ int          g_cellstart[BB * 257];
__device__ unsigned int g_mask[BB * TOPK * 32];
__device__ unsigned int g_wnz[BB * TOPK];

// ---------------- K1: WIDE score + smem histogram (half batch) ----------------
__global__ __launch_bounds__(256) void k_score(const float* __restrict__ x, int b0) {
    __shared__ unsigned int h[NB];
    int b = b0 + blockIdx.y, t = threadIdx.x;
    h[t] = 0u;
    __syncthreads();
#pragma unroll
    for (int a = 0; a < 4; ++a) {
        int n = blockIdx.x * 1024 + a * 256 + t;
        if (n < NN) {
            const float4* row = (const float4*)(x + (long)(b * NN + n) * 16);
            float s = row[1].x * row[3].w;
            if (s > CONF) {
                g_scores[b * NN + n] = s;   // sub-CONF slots stay 0 (zero-init) — same selection
                int bin = min((int)((s - CONF) * BSCALE), NB - 1);
                atomicAdd(&h[bin], 1u);
            }
        }
    }
    __syncthreads();
    unsigned int c = h[t];
    if (c) atomicAdd(&g_hist[b * NB + t], c);
}

// ---------------- K2: threshold + 1-read compact + hybrid-bitonic + bin -----
__global__ __launch_bounds__(1024) void k_topk(const float* __restrict__ x, int b0) {
    __shared__ unsigned long long sk[CAP];
    __shared__ int sT, wcnt[32], woff[32];
    __shared__ unsigned int wtot[8], wexc[8];
    __shared__ int counts[256], scanbuf[256], cstart[257];

    int b = b0 + blockIdx.x, t = threadIdx.x;
    int w = t >> 5, lane = t & 31;

    if (t == 0) sT = 0;
    unsigned int s = 0u;
    if (t < NB) {
        unsigned int v = g_hist[b * NB + t];
        g_hist[b * NB + t] = 0u;
        s = v;
#pragma unroll
        for (int off = 1; off < 32; off <<= 1) {
            unsigned int y = __shfl_down_sync(0xffffffffu, s, off);
            if (lane + off < 32) s += y;
        }
        if (lane == 0) wtot[w] = s;
    }
    __syncthreads();
    if (t < 8) {
        unsigned int q = wtot[t];
        unsigned int qs = q;
#pragma unroll
        for (int off = 1; off < 8; off <<= 1) {
            unsigned int y = __shfl_down_sync(0x000000ffu, qs, off);
            if (t + off < 8) qs += y;
        }
        wexc[t] = qs - q;
    }
    __syncthreads();
    if (t < NB) {
        unsigned int suf = s + wexc[w];
        if (suf >= TOPK) atomicMax(&sT, t);
    }
    sk[t] = 0ULL; sk[t + 1024] = 0ULL;
    __syncthreads();

    int T = sT;
    int base = w * CHUNK;
    int lim = min(base + CHUNK, NN);
    unsigned int selbits = 0u;
    {
        int cnt = 0;
        for (int it = 0; it < 25; ++it) {
            int n = base + it * 32 + lane;
            bool sel = false;
            if (n < lim) {
                float sc = g_scores[b * NN + n];
                if (sc > CONF) {
                    int bin = min((int)((sc - CONF) * BSCALE), NB - 1);
                    sel = (bin >= T);
                }
            }
            selbits |= sel ? (1u << it) : 0u;
            cnt += __popc(__ballot_sync(0xffffffffu, sel));
        }
        if (lane == 0) wcnt[w] = cnt;
    }
    __syncthreads();
    if (t < 32) {
        int vv = wcnt[t], p = vv;
#pragma unroll
        for (int off = 1; off < 32; off <<= 1) {
            int y = __shfl_up_sync(0xffffffffu, p, off);
            if (t >= off) p += y;
        }
        woff[t] = p - vv;
    }
    __syncthreads();
    {
        int off = woff[w];
        int run = 0;
        for (int it = 0; it < 25; ++it) {
            bool sel = (selbits >> it) & 1u;
            unsigned int m = __ballot_sync(0xffffffffu, sel);
            if (sel) {
                int n = base + it * 32 + lane;
                float sc = g_scores[b * NN + n];
                int pos = off + run + __popc(m & ((1u << lane) - 1u));
                if (pos < CAP) {
                    sk[pos] = ((unsigned long long)__float_as_uint(sc) << 32) |
                              (unsigned long long)(0xFFFFFFFFu - (unsigned)n);
                }
            }
            run += __popc(m);
        }
    }
    __syncthreads();

    // hybrid bitonic desc (2048 u64)
    {
        int w64 = w << 6;
        int ia = w64 + lane, ic = ia + 32;
        unsigned long long a = sk[ia], c = sk[ic];
#pragma unroll
        for (int k = 2; k <= 32; k <<= 1) {
#pragma unroll
            for (int j = 16; j >= 1; j >>= 1) {
                if (j < k) {
                    {
                        unsigned long long o = __shfl_xor_sync(0xffffffffu, a, j);
                        bool keepMax = (((ia & j) == 0) == ((ia & k) == 0));
                        a = keepMax ? (a > o ? a : o) : (a < o ? a : o);
                    }
                    {
                        unsigned long long o = __shfl_xor_sync(0xffffffffu, c, j);
                        bool keepMax = (((ic & j) == 0) == ((ic & k) == 0));
                        c = keepMax ? (c > o ? c : o) : (c < o ? c : o);
                    }
                }
            }
        }
        {
            bool desc = ((ia & 64) == 0);
            unsigned long long hi = a > c ? a : c, lo = a > c ? c : a;
            a = desc ? hi : lo; c = desc ? lo : hi;
#pragma unroll
            for (int j = 16; j >= 1; j >>= 1) {
                {
                    unsigned long long o = __shfl_xor_sync(0xffffffffu, a, j);
                    bool keepMax = (((ia & j) == 0) == desc);
                    a = keepMax ? (a > o ? a : o) : (a < o ? a : o);
                }
                {
                    unsigned long long o = __shfl_xor_sync(0xffffffffu, c, j);
                    bool keepMax = (((ic & j) == 0) == desc);
                    c = keepMax ? (c > o ? c : o) : (c < o ? c : o);
                }
            }
        }
        sk[ia] = a; sk[ic] = c;
    }
    __syncthreads();
    for (int k = 128; k <= CAP; k <<= 1) {
        for (int j = k >> 1; j >= 64; j >>= 1) {
#pragma unroll
            for (int ee = 0; ee < 2; ++ee) {
                int e = t + ee * 1024;
                int ixj = e ^ j;
                if (ixj > e) {
                    unsigned long long a = sk[e], c = sk[ixj];
                    bool desc = ((e & k) == 0);
                    if (desc ? (a < c) : (a > c)) { sk[e] = c; sk[ixj] = a; }
                }
            }
            __syncthreads();
        }
        {
            int w64 = w << 6;
            int ia = w64 + lane, ic = ia + 32;
            unsigned long long a = sk[ia], c = sk[ic];
            bool desc = ((ia & k) == 0);
            unsigned long long hi = a > c ? a : c, lo = a > c ? c : a;
            a = desc ? hi : lo; c = desc ? lo : hi;
#pragma unroll
            for (int j = 16; j >= 1; j >>= 1) {
                {
                    unsigned long long o = __shfl_xor_sync(0xffffffffu, a, j);
                    bool keepMax = (((ia & j) == 0) == desc);
                    a = keepMax ? (a > o ? a : o) : (a < o ? a : o);
                }
                {
                    unsigned long long o = __shfl_xor_sync(0xffffffffu, c, j);
                    bool keepMax = (((ic & j) == 0) == desc);
                    c = keepMax ? (c > o ? c : o) : (c < o ? c : o);
                }
            }
            sk[ia] = a; sk[ic] = c;
        }
        __syncthreads();
    }

    unsigned long long key = sk[t];
    float sc = __uint_as_float((unsigned)(key >> 32));
    int idx = (key == 0ULL) ? 0 : (int)(0xFFFFFFFFu - (unsigned)(key & 0xFFFFFFFFu));
    if (idx < 0 || idx >= NN) idx = 0;
    g_topscore[b * TOPK + t] = (key == 0ULL) ? 0.0f : sc;
    g_topidx[b * TOPK + t] = idx;
    const float4* row = (const float4*)(x + (long)(b * NN + idx) * 16);
    float4 c0 = row[0];
    float hw = c0.z * 0.5f, hh = c0.w * 0.5f;
    float4 box = make_float4(c0.x - hw, c0.y - hh, c0.x + hw, c0.y + hh);
    float sv = 0.45f * (fmaxf(box.z - box.x, 0.0f) * fmaxf(box.w - box.y, 0.0f));
    int cellx = min(15, max(0, (int)(c0.x * 0.025f)));
    int celly = min(15, max(0, (int)(c0.y * 0.025f)));
    int cell = celly * 16 + cellx;

    if (t < 256) counts[t] = 0;
    __syncthreads();
    atomicAdd(&counts[cell], 1);
    __syncthreads();
    if (t < 256) scanbuf[t] = counts[t];
    __syncthreads();
    for (int off = 1; off < 256; off <<= 1) {
        int add = 0;
        if (t < 256 && t >= off) add = scanbuf[t - off];
        __syncthreads();
        if (t < 256) scanbuf[t] += add;
        __syncthreads();
    }
    if (t == 0) cstart[0] = 0;
    if (t < 256) { cstart[t + 1] = scanbuf[t]; counts[t] = (t == 0) ? 0 : scanbuf[t - 1]; }
    __syncthreads();
    {
        int pos = atomicAdd(&counts[cell], 1);
        g_sbox[b * TOPK + pos] = box;
        g_saux[b * TOPK + pos] = make_uint2(__float_as_uint(sv), (unsigned)t);
    }
    if (t < 257) g_cellstart[b * 257 + t] = cstart[t];
}

// ---------------- K3: sparse suppression-mask, 8 threads per entry ----------
__global__ __launch_bounds__(1024) void k_pairs(int b0) {
    __shared__ float4       sbox[TOPK];
    __shared__ uint2        sax[TOPK];
    __shared__ int          cs[257];
    __shared__ unsigned int rows[128 * 33];

    int b = b0 + blockIdx.y, t = threadIdx.x;
    int le = t >> 3;
    int q  = t & 7;
    int s  = blockIdx.x * 128 + le;

    for (int e = t; e < TOPK; e += 1024) {
        sbox[e] = g_sbox[b * TOPK + e];
        sax[e]  = g_saux[b * TOPK + e];
    }
    for (int e = t; e < 257; e += 1024) cs[e] = g_cellstart[b * 257 + e];
    __syncthreads();

    unsigned int* rowp = &rows[le * 33];
    for (int ww = q; ww < 32; ww += 8) rowp[ww] = 0u;
    __syncwarp();

    float4 bs = sbox[s];
    uint2 axs = sax[s];
    float u = __uint_as_float(axs.x);
    int rs = (int)axs.y;

    int cl = max(0, (int)((bs.x - 64.5f) * 0.025f));
    int cr = min(15, (int)((bs.z + 64.5f) * 0.025f));
    int ct = max(0, (int)((bs.y - 64.5f) * 0.025f));
    int cb = min(15, (int)((bs.w + 64.5f) * 0.025f));

    for (int cy = ct; cy <= cb; ++cy) {
        int e0 = cs[cy * 16 + cl];
        int e1 = cs[cy * 16 + cr + 1];
#pragma unroll 2
        for (int e = e0 + q; e < e1; e += 8) {
            float4 be = sbox[e];
            uint2 axe = sax[e];
            float ix1 = fmaxf(bs.x, be.x), iy1 = fmaxf(bs.y, be.y);
            float ix2 = fminf(bs.z, be.z), iy2 = fminf(bs.w, be.w);
            float inter = fmaxf(ix2 - ix1, 0.0f) * fmaxf(iy2 - iy1, 0.0f);
            float sden = u + __uint_as_float(axe.x);
            float diff = fmaf(1.45f, inter, -sden);
            bool bit;
            if (fabsf(diff) <= 2e-5f * sden) {
                float ai = fmaxf(bs.z - bs.x, 0.0f) * fmaxf(bs.w - bs.y, 0.0f);
                float aj = fmaxf(be.z - be.x, 0.0f) * fmaxf(be.w - be.y, 0.0f);
                float den = (ai + aj - inter) + 1e-9f;
                bit = (__fdiv_rn(inter, den) > IOUT);
            } else {
                bit = (diff > 0.0f);
            }
            int re = (int)axe.y;
            if (bit && re > rs) atomicOr(&rowp[re >> 5], 1u << (re & 31));
        }
    }
    __syncwarp();

    if (q == 0) {
        unsigned int wm = 0u;
#pragma unroll
        for (int ww = 0; ww < 32; ++ww) wm |= (rowp[ww] != 0u) ? (1u << ww) : 0u;
        g_wnz[b * TOPK + rs] = wm;
        if (wm) {
            unsigned int* orow = &g_mask[((long)(b * TOPK + rs)) * 32];
#pragma unroll
            for (int ww = 0; ww < 32; ++ww) orow[ww] = rowp[ww];
        }
    }
}

// ---------------- K4: rank-indexed sparse greedy scan + output ----------------
__global__ __launch_bounds__(1024) void k_scan_out(const float* __restrict__ x,
                                                   float* __restrict__ out, int b0) {
    extern __shared__ unsigned int srow[];
    __shared__ unsigned int validw[32];
    __shared__ unsigned int harw[32];
    __shared__ unsigned int keepw[32];

    int b = b0 + blockIdx.x, t = threadIdx.x;
    int w = t >> 5, lane = t & 31;

    float sc = g_topscore[b * TOPK + t];
    unsigned int vb = __ballot_sync(0xffffffffu, sc > 0.0f);
    if (lane == 0) validw[w] = vb;

    bool nzf = (g_wnz[b * TOPK + t] != 0u);
    unsigned int hb = __ballot_sync(0xffffffffu, nzf);
    if (lane == 0) harw[w] = hb;

    if (nzf) {
        const uint4* src = (const uint4*)&g_mask[((long)(b * TOPK + t)) * 32];
        uint4* dst = (uint4*)&srow[t * RSTR];
#pragma unroll
        for (int i = 0; i < 8; ++i) dst[i] = src[i];
    }
    __syncthreads();

    if (t < 32) {
        unsigned int removed = 0u;
        unsigned int vwl = validw[lane];
        for (int wi = 0; wi < 32; ++wi) {
            unsigned int alive = __shfl_sync(0xffffffffu, vwl & ~removed, wi);
            unsigned int evt = alive & harw[wi];
            while (evt) {
                int j = __ffs(evt) - 1;
                evt &= evt - 1u;
                int rbase = ((wi << 5) + j) * RSTR;
                unsigned int rw = srow[rbase + lane];
                unsigned int au = srow[rbase + wi];
                removed |= rw;
                alive &= ~au;
                evt &= alive;
            }
            if (lane == 0) keepw[wi] = alive;
        }
    }
    __syncthreads();

    unsigned int kept = (keepw[t >> 5] >> (t & 31)) & 1u;
    float4* orow = (float4*)(out + (long)(b * TOPK + t) * 16);
    if (kept) {
        int idx = g_topidx[b * TOPK + t];
        const float4* row = (const float4*)(x + (long)(b * NN + idx) * 16);
        float4 c0 = row[0], c1 = row[1], c2 = row[2], c3 = row[3];
        float hw = c0.z * 0.5f, hh = c0.w * 0.5f;
        orow[0] = make_float4(c0.x - hw, c0.y - hh, c0.x + hw, c0.y + hh);
        orow[1] = make_float4(sc, c1.y, c1.z, c1.w);
        orow[2] = c2;
        orow[3] = make_float4(c3.x, c3.y, c3.z, 0.0f);
    } else {
        float4 z = make_float4(0.0f, 0.0f, 0.0f, 0.0f);
        orow[0] = z; orow[1] = z; orow[2] = z; orow[3] = z;
    }
}

// ---------------- launch: two staggered half-batch chains ----------------
extern "C" void kernel_launch(void* const* d_in, const int* in_sizes, int n_in,
                              void* d_out, int out_size) {
    const float* x = (const float*)d_in[0];
    float* out = (float*)d_out;
    (void)in_sizes; (void)n_in; (void)out_size;

    const int scan_smem = TOPK * RSTR * 4;   // 147456 bytes
    cudaFuncSetAttribute(k_scan_out, cudaFuncAttributeMaxDynamicSharedMemorySize, scan_smem);

    cudaStream_t s2;
    cudaStreamCreateWithFlags(&s2, cudaStreamNonBlocking);
    cudaEvent_t eScoreA, eJoin;
    cudaEventCreateWithFlags(&eScoreA, cudaEventDisableTiming);
    cudaEventCreateWithFlags(&eJoin, cudaEventDisableTiming);

    dim3 gs((NN + 1023) / 1024, HB);
    dim3 gp(8, HB);

    // ---- half A on the capture (default) stream ----
    k_score<<<gs, 256>>>(x, 0);
    cudaEventRecord(eScoreA, 0);                 // fork point: B starts after A.score
    k_topk<<<HB, 1024>>>(x, 0);
    k_pairs<<<gp, 1024>>>(0);
    k_scan_out<<<HB, 1024, scan_smem>>>(x, out, 0);

    // ---- half B on side stream, staggered one stage behind ----
    cudaStreamWaitEvent(s2, eScoreA, 0);
    k_score<<<gs, 256, 0, s2>>>(x, HB);
    k_topk<<<HB, 1024, 0, s2>>>(x, HB);
    k_pairs<<<gp, 1024, 0, s2>>>(HB);
    k_scan_out<<<HB, 1024, scan_smem, s2>>>(x, out, HB);

    // ---- join ----
    cudaEventRecord(eJoin, s2);
    cudaStreamWaitEvent(0, eJoin, 0);

    cudaEventDestroy(eScoreA);
    cudaEventDestroy(eJoin);
    cudaStreamDestroy(s2);
}